// round 3
// baseline (speedup 1.0000x reference)
#include <cuda_runtime.h>
#include <cuda_bf16.h>

#define BATCH   256
#define NSCORES 50000
#define TOPK    20
#define NBINS   2048
#define RLO     (-7.0f)
#define RHI     (7.0f)
#define THREADS 512

// Cross-kernel scratch (no allocation allowed): ranks per (row, j)
__device__ float g_ranks[BATCH * TOPK];

// Bit-trick seed + 2 Newton iterations. Returns approximately -1/d for d > 0.
// (Sign folded so the accumulate can be a single FFMA; negate at the end.)
__device__ __forceinline__ float fast_neg_rcp(float d) {
    float r0 = __uint_as_float(0x7EF311C3u - __float_as_uint(d));
    float t1 = fmaf(d, r0, -2.0f);   // d*r0 - 2
    float m1 = r0 * t1;              // = -r1
    float t2 = fmaf(d, m1, 2.0f);    // 2 - d*r1
    return m1 * t2;                  // = -r2 ~ -1/d  (rel err ~6e-6)
}

__global__ void __launch_bounds__(THREADS, 2)
rank_kernel(const float* __restrict__ scores_top,
            const float* __restrict__ scores)
{
    __shared__ int   hist[NBINS];
    __shared__ float red[THREADS / 32][TOPK];

    const int b    = blockIdx.x;
    const int tid  = threadIdx.x;
    const int lane = tid & 31;
    const int warp = tid >> 5;

    const float SCALE    = (float)NBINS / (RHI - RLO);
    const float INVSCALE = (RHI - RLO) / (float)NBINS;

    // C[j] = exp(top[b][j])  (broadcast loads, tiny)
    float C[TOPK];
    const float* trow = scores_top + b * TOPK;
#pragma unroll
    for (int j = 0; j < TOPK; j++) C[j] = __expf(trow[j]);

    for (int i = tid; i < NBINS; i += THREADS) hist[i] = 0;
    __syncthreads();

    // ---- Pass 1: integer histogram of this row's scores (deterministic) ----
    const float4* row4 = (const float4*)(scores + (size_t)b * NSCORES);
    for (int i = tid; i < NSCORES / 4; i += THREADS) {
        float4 v = row4[i];
        float xs0 = v.x, xs1 = v.y, xs2 = v.z, xs3 = v.w;
        float u0 = fminf(fmaxf(fmaf(xs0, SCALE, -RLO * SCALE), 0.0f), (float)(NBINS - 1));
        float u1 = fminf(fmaxf(fmaf(xs1, SCALE, -RLO * SCALE), 0.0f), (float)(NBINS - 1));
        float u2 = fminf(fmaxf(fmaf(xs2, SCALE, -RLO * SCALE), 0.0f), (float)(NBINS - 1));
        float u3 = fminf(fmaxf(fmaf(xs3, SCALE, -RLO * SCALE), 0.0f), (float)(NBINS - 1));
        atomicAdd(&hist[(int)u0], 1);
        atomicAdd(&hist[(int)u1], 1);
        atomicAdd(&hist[(int)u2], 1);
        atomicAdd(&hist[(int)u3], 1);
    }
    __syncthreads();

    // ---- Pass 2: acc[j] -= cnt_b * sigmoid(c_b - t_j) over bins ----
    float acc[TOPK];
#pragma unroll
    for (int j = 0; j < TOPK; j++) acc[j] = 0.0f;

    for (int bin = tid; bin < NBINS; bin += THREADS) {
        int cnt = hist[bin];
        if (cnt == 0) continue;
        float cf = (float)cnt;
        float c  = fmaf((float)bin + 0.5f, INVSCALE, RLO);
        float E  = __expf(-c);                 // one MUFU per bin, shared by 20 j
#pragma unroll
        for (int j = 0; j < TOPK; j++) {
            float d = fmaf(C[j], E, 1.0f);     // 1 + e^{t_j - c_b}
            float w = fast_neg_rcp(d);         // ~ -sigmoid(c_b - t_j)
            acc[j] = fmaf(cf, w, acc[j]);
        }
    }

    // ---- Block reduction of the 20 accumulators ----
#pragma unroll
    for (int j = 0; j < TOPK; j++) {
        float v = acc[j];
#pragma unroll
        for (int off = 16; off; off >>= 1)
            v += __shfl_xor_sync(0xffffffffu, v, off);
        if (lane == 0) red[warp][j] = v;
    }
    __syncthreads();

    if (tid < TOPK) {
        float s = 0.0f;
#pragma unroll
        for (int w = 0; w < THREADS / 32; w++) s += red[w][tid];
        // acc held negative sums: ranks = sum(sigmoid) + 0.5 = 0.5 - s
        g_ranks[b * TOPK + tid] = 0.5f - s;
    }
}

__global__ void epilogue_kernel(const float* __restrict__ labels,
                                float* __restrict__ out)
{
    const int b = blockIdx.x;
    const int j = threadIdx.x;           // 0..31, lanes >= TOPK inert
    const bool valid = (j < TOPK);
    const unsigned mask = 0xffffffffu;

    float rank = valid ? g_ranks[b * TOPK + j] : 1.0f;
    float lab  = valid ? labels[b * TOPK + j]  : 0.0f;

    float d  = log2f(rank + 1.0f);
    float dg = valid ? (lab / d) : 0.0f;

    // inclusive scan -> dcg
    float dcg = dg;
#pragma unroll
    for (int off = 1; off < 32; off <<= 1) {
        float y = __shfl_up_sync(mask, dcg, off);
        if (j >= off) dcg += y;
    }

    // k_sum
    float ls = lab;
#pragma unroll
    for (int off = 16; off; off >>= 1) ls += __shfl_xor_sync(mask, ls, off);
    int ksum = __float2int_rn(ls);

    // idcg inclusive scan: idcg[j] = sum_{i<=j} 1/log2(i+2)
    float ic = valid ? (1.0f / log2f((float)j + 2.0f)) : 0.0f;
    float idcg = ic;
#pragma unroll
    for (int off = 1; off < 32; off <<= 1) {
        float y = __shfl_up_sync(mask, idcg, off);
        if (j >= off) idcg += y;
    }

    int kcl = min(ksum, j + 1);
    int idx = kcl - 1;
    if (idx < 0) idx = 0;                 // only when ksum==0 -> dcg==0 anyway
    float denom = __shfl_sync(mask, idcg, idx);

    if (valid) out[b * TOPK + j] = dcg / denom;
}

extern "C" void kernel_launch(void* const* d_in, const int* in_sizes, int n_in,
                              void* d_out, int out_size)
{
    // metadata order: scores_top (B*TOPK), scores (B*N), labels (B*TOPK).
    // Identify `scores` by its unique size; keep relative order of the others.
    int si = 1;
    for (int i = 0; i < n_in; i++)
        if (in_sizes[i] == BATCH * NSCORES) { si = i; break; }
    int rest[2], r = 0;
    for (int i = 0; i < n_in && r < 2; i++)
        if (i != si) rest[r++] = i;

    const float* scores_top = (const float*)d_in[rest[0]];
    const float* scores     = (const float*)d_in[si];
    const float* labels     = (const float*)d_in[rest[1]];
    float* out = (float*)d_out;

    rank_kernel<<<BATCH, THREADS>>>(scores_top, scores);
    epilogue_kernel<<<BATCH, 32>>>(labels, out);
}